// round 14
// baseline (speedup 1.0000x reference)
#include <cuda_runtime.h>
#include <cstdint>

// BaseVectorQuantizer, exact: dist_k = fp32( fp32(||x||^2+||e_k||^2) - 2*dot ).
// V=3 vectors/thread (192 x-regs): each broadcast LDS.128 feeds 6 fma.rn.f32x2,
// cutting smem-port demand to 2/3 of the fma-pipe demand -> fma is sole binder.
// Rounding chain identical to the R13 zero-flip chain.

#define NUM_K 1024
#define DIM   64
#define CHUNK 256
#define TPB   128
#define HW    4096
#define NVEC  131072
#define V     3
#define VPB   (V * TPB)        // 384

typedef unsigned long long ull_t;

__device__ float g_esq[NUM_K];

__global__ void esq_kernel(const float* __restrict__ cb) {
    int k = blockIdx.x * blockDim.x + threadIdx.x;
    if (k < NUM_K) {
        float s = 0.f;
        #pragma unroll
        for (int i = 0; i < DIM; i++) {
            float v = cb[k * DIM + i];
            s = __fadd_rn(s, __fmul_rn(v, v));
        }
        g_esq[k] = s;
    }
}

__global__ __launch_bounds__(TPB, 2) void vq_kernel(const float* __restrict__ x_in,
                                                    const float* __restrict__ cb,
                                                    float* __restrict__ out) {
    __shared__ __align__(16) float se[CHUNK * DIM];   // 64 KB row-major
    __shared__ float sesq[CHUNK];

    const int t    = threadIdx.x;
    const int base = blockIdx.x * VPB;

    // per-sub-vector ids; last block clamps invalid rows (store-predicated)
    int  vid[V];
    bool vok[V];
    #pragma unroll
    for (int j = 0; j < V; j++) {
        int v0 = base + j * TPB;
        vok[j] = (v0 < NVEC);                 // 128-aligned -> warp-uniform
        int vc = vok[j] ? v0 : (NVEC - TPB);
        vid[j] = vc + t;
    }

    // x as natural (x_2p, x_2p+1) packed f32x2 pairs; xsq sequential fp32
    ull_t x2[V][DIM / 2];
    float xsq[V];
    #pragma unroll
    for (int j = 0; j < V; j++) {
        const int b = vid[j] >> 12;
        const int s = vid[j] & (HW - 1);
        const float* xp = x_in + (size_t)b * (DIM * HW) + s;
        float acc = 0.f;
        #pragma unroll
        for (int p = 0; p < DIM / 2; p++) {
            float v0 = xp[(2 * p) * HW], v1 = xp[(2 * p + 1) * HW];
            acc = __fadd_rn(acc, __fmul_rn(v0, v0));
            acc = __fadd_rn(acc, __fmul_rn(v1, v1));
            asm("mov.b64 %0, {%1, %2};" : "=l"(x2[j][p]) : "f"(v0), "f"(v1));
        }
        xsq[j] = acc;
    }

    uint32_t se_base;
    asm("{ .reg .u64 t; cvta.to.shared.u64 t, %1; cvt.u32.u64 %0, t; }"
        : "=r"(se_base) : "l"(se));

    float best[V];
    int   bk[V];
    #pragma unroll
    for (int j = 0; j < V; j++) { best[j] = 3.4e38f; bk[j] = 0; }

    for (int c = 0; c < NUM_K / CHUNK; c++) {
        __syncthreads();
        const float4* src = reinterpret_cast<const float4*>(cb + c * CHUNK * DIM);
        float4* dst = reinterpret_cast<float4*>(se);
        #pragma unroll
        for (int j = 0; j < (CHUNK * DIM / 4) / TPB; j++)
            dst[j * TPB + t] = src[j * TPB + t];
        #pragma unroll
        for (int j = 0; j < CHUNK / TPB; j++)
            sesq[j * TPB + t] = g_esq[c * CHUNK + j * TPB + t];
        __syncthreads();

        #pragma unroll 1
        for (int k = 0; k < CHUNK; k++) {
            ull_t a0[V], a1[V];
            #pragma unroll
            for (int j = 0; j < V; j++) { a0[j] = 0ull; a1[j] = 0ull; }
            const uint32_t addr = se_base + k * (DIM * 4);
            #pragma unroll
            for (int d4 = 0; d4 < DIM / 4; d4++) {
                ull_t e0, e1;   // (e_{4d},e_{4d+1}), (e_{4d+2},e_{4d+3})
                asm("ld.shared.v2.u64 {%0, %1}, [%2];"
                    : "=l"(e0), "=l"(e1) : "r"(addr + d4 * 16));
                #pragma unroll
                for (int j = 0; j < V; j++) {
                    asm("fma.rn.f32x2 %0, %1, %2, %0;"
                        : "+l"(a0[j]) : "l"(x2[j][2 * d4]),     "l"(e0));
                    asm("fma.rn.f32x2 %0, %1, %2, %0;"
                        : "+l"(a1[j]) : "l"(x2[j][2 * d4 + 1]), "l"(e1));
                }
            }
            const float esq = sesq[k];
            const int   kk  = c * CHUNK + k;
            #pragma unroll
            for (int j = 0; j < V; j++) {
                ull_t sa;
                asm("add.rn.f32x2 %0, %1, %2;" : "=l"(sa) : "l"(a0[j]), "l"(a1[j]));
                float lo, hi;
                asm("mov.b64 {%0, %1}, %2;" : "=f"(lo), "=f"(hi) : "l"(sa));
                float dot = __fadd_rn(lo, hi);
                // dist = round(T - 2*dot), T = round(xsq+esq); 2*dot exact
                float d = fmaf(-2.f, dot, __fadd_rn(xsq[j], esq));
                bool p = d < best[j];            // branchless, ascending-k tie-break
                best[j] = p ? d : best[j];
                bk[j]   = p ? kk : bk[j];
            }
        }
    }

    // STE epilogue: out = x + (e - x) fp32, BCHW scatter (store-predicated)
    #pragma unroll
    for (int j = 0; j < V; j++) {
        if (!vok[j]) continue;
        const float4* row = reinterpret_cast<const float4*>(cb + (size_t)bk[j] * DIM);
        const int b = vid[j] >> 12;
        const int s = vid[j] & (HW - 1);
        float* op = out + (size_t)b * (DIM * HW) + s;
        #pragma unroll
        for (int q = 0; q < DIM / 4; q++) {
            float4 qv = __ldg(row + q);
            float y0, y1, y2, y3;
            asm("mov.b64 {%0, %1}, %2;" : "=f"(y0), "=f"(y1) : "l"(x2[j][2 * q]));
            asm("mov.b64 {%0, %1}, %2;" : "=f"(y2), "=f"(y3) : "l"(x2[j][2 * q + 1]));
            op[(4 * q + 0) * HW] = __fadd_rn(y0, __fsub_rn(qv.x, y0));
            op[(4 * q + 1) * HW] = __fadd_rn(y1, __fsub_rn(qv.y, y1));
            op[(4 * q + 2) * HW] = __fadd_rn(y2, __fsub_rn(qv.z, y2));
            op[(4 * q + 3) * HW] = __fadd_rn(y3, __fsub_rn(qv.w, y3));
        }
    }
}

extern "C" void kernel_launch(void* const* d_in, const int* in_sizes, int n_in,
                              void* d_out, int out_size) {
    const float* x  = (const float*)d_in[0];
    const float* cb = (const float*)d_in[1];
    if (n_in >= 2 && in_sizes[0] == NUM_K * DIM && in_sizes[1] == NVEC * DIM) {
        const float* t = x; x = cb; cb = t;
    }
    float* out = (float*)d_out;

    esq_kernel<<<(NUM_K + 127) / 128, 128>>>(cb);
    vq_kernel<<<(NVEC + VPB - 1) / VPB, TPB>>>(x, cb, out);
}

// round 15
// speedup vs baseline: 1.0538x; 1.0538x over previous
#include <cuda_runtime.h>
#include <cstdint>

// BaseVectorQuantizer, exact: dist_k = fp32( fp32(||x||^2+||e_k||^2) - 2*dot ).
// V=2, natural (x_2p,x_2p+1) f32x2 pairs, row-major codebook in smem.
// Inner FFMA2s reordered so consecutive instructions share the e operand in
// the same slot -> operand-reuse cache (.reuse) skips the RF bank read,
// attacking the 3-even/3-odd bank-conflict rt=3 on packed FFMA2.
// Accumulation order per chain identical to R13 (zero-flip validated).

#define NUM_K 1024
#define DIM   64
#define CHUNK 256
#define TPB   128
#define HW    4096
#define NVEC  131072
#define VPB   256

typedef unsigned long long ull_t;

__device__ float g_esq[NUM_K];

__global__ void esq_kernel(const float* __restrict__ cb) {
    int k = blockIdx.x * blockDim.x + threadIdx.x;
    if (k < NUM_K) {
        float s = 0.f;
        #pragma unroll
        for (int i = 0; i < DIM; i++) {
            float v = cb[k * DIM + i];
            s = __fadd_rn(s, __fmul_rn(v, v));
        }
        g_esq[k] = s;
    }
}

__global__ __launch_bounds__(TPB, 2) void vq_kernel(const float* __restrict__ x_in,
                                                    const float* __restrict__ cb,
                                                    float* __restrict__ out) {
    __shared__ __align__(16) float se[CHUNK * DIM];   // 64 KB row-major
    __shared__ float sesq[CHUNK];

    const int t    = threadIdx.x;
    const int base = blockIdx.x * VPB;
    const int b    = base >> 12;
    const int sA   = (base & (HW - 1)) + t;
    const float* xpA = x_in + (size_t)b * (DIM * HW) + sA;
    const float* xpB = xpA + TPB;

    // x for both vectors as natural packed f32x2 dim-pairs; xsq sequential fp32
    ull_t xA2[DIM / 2], xB2[DIM / 2];
    float xsqA = 0.f, xsqB = 0.f;
    #pragma unroll
    for (int p = 0; p < DIM / 2; p++) {
        float a0 = xpA[(2 * p) * HW], a1 = xpA[(2 * p + 1) * HW];
        float c0 = xpB[(2 * p) * HW], c1 = xpB[(2 * p + 1) * HW];
        xsqA = __fadd_rn(xsqA, __fmul_rn(a0, a0));
        xsqA = __fadd_rn(xsqA, __fmul_rn(a1, a1));
        xsqB = __fadd_rn(xsqB, __fmul_rn(c0, c0));
        xsqB = __fadd_rn(xsqB, __fmul_rn(c1, c1));
        asm("mov.b64 %0, {%1, %2};" : "=l"(xA2[p]) : "f"(a0), "f"(a1));
        asm("mov.b64 %0, {%1, %2};" : "=l"(xB2[p]) : "f"(c0), "f"(c1));
    }

    uint32_t se_base;
    asm("{ .reg .u64 t; cvta.to.shared.u64 t, %1; cvt.u32.u64 %0, t; }"
        : "=r"(se_base) : "l"(se));

    float bestA = 3.4e38f, bestB = 3.4e38f;
    int   bkA = 0, bkB = 0;

    for (int c = 0; c < NUM_K / CHUNK; c++) {
        __syncthreads();
        const float4* src = reinterpret_cast<const float4*>(cb + c * CHUNK * DIM);
        float4* dst = reinterpret_cast<float4*>(se);
        #pragma unroll
        for (int j = 0; j < (CHUNK * DIM / 4) / TPB; j++)
            dst[j * TPB + t] = src[j * TPB + t];
        #pragma unroll
        for (int j = 0; j < CHUNK / TPB; j++)
            sesq[j * TPB + t] = g_esq[c * CHUNK + j * TPB + t];
        __syncthreads();

        #pragma unroll 2
        for (int k = 0; k < CHUNK; k++) {
            ull_t a0 = 0ull, a1 = 0ull, b0 = 0ull, b1 = 0ull;
            const uint32_t addr = se_base + k * (DIM * 4);
            #pragma unroll
            for (int d4 = 0; d4 < DIM / 4; d4++) {
                ull_t e0, e1;   // (e_{4d},e_{4d+1}), (e_{4d+2},e_{4d+3})
                asm("ld.shared.v2.u64 {%0, %1}, [%2];"
                    : "=l"(e0), "=l"(e1) : "r"(addr + d4 * 16));
                // e0 consecutive in the same slot (reuse), then e1 likewise
                asm("fma.rn.f32x2 %0, %1, %2, %0;" : "+l"(a0) : "l"(xA2[2 * d4]),     "l"(e0));
                asm("fma.rn.f32x2 %0, %1, %2, %0;" : "+l"(b0) : "l"(xB2[2 * d4]),     "l"(e0));
                asm("fma.rn.f32x2 %0, %1, %2, %0;" : "+l"(a1) : "l"(xA2[2 * d4 + 1]), "l"(e1));
                asm("fma.rn.f32x2 %0, %1, %2, %0;" : "+l"(b1) : "l"(xB2[2 * d4 + 1]), "l"(e1));
            }
            ull_t sa, sb;
            asm("add.rn.f32x2 %0, %1, %2;" : "=l"(sa) : "l"(a0), "l"(a1));
            asm("add.rn.f32x2 %0, %1, %2;" : "=l"(sb) : "l"(b0), "l"(b1));
            float alo, ahi, blo, bhi;
            asm("mov.b64 {%0, %1}, %2;" : "=f"(alo), "=f"(ahi) : "l"(sa));
            asm("mov.b64 {%0, %1}, %2;" : "=f"(blo), "=f"(bhi) : "l"(sb));
            const float esq  = sesq[k];
            const float dotA = __fadd_rn(alo, ahi);
            const float dotB = __fadd_rn(blo, bhi);
            // dist = round(T - 2*dot), T = round(xsq+esq); 2*dot exact ->
            // fmaf(-2,dot,T) rounds once == reference fsub(T, 2dot)
            const float dA = fmaf(-2.f, dotA, __fadd_rn(xsqA, esq));
            const float dB = fmaf(-2.f, dotB, __fadd_rn(xsqB, esq));
            const int kk = c * CHUNK + k;
            bool pA = dA < bestA;            // branchless, ascending-k tie-break
            bool pB = dB < bestB;
            bestA = pA ? dA : bestA;  bkA = pA ? kk : bkA;
            bestB = pB ? dB : bestB;  bkB = pB ? kk : bkB;
        }
    }

    // STE epilogue: out = x + (e - x) fp32, BCHW scatter
    const float4* rowA = reinterpret_cast<const float4*>(cb + (size_t)bkA * DIM);
    const float4* rowB = reinterpret_cast<const float4*>(cb + (size_t)bkB * DIM);
    float* opA = out + (size_t)b * (DIM * HW) + sA;
    float* opB = opA + TPB;
    #pragma unroll
    for (int j = 0; j < DIM / 4; j++) {
        float4 qA = __ldg(&rowA[j]);
        float4 qB = __ldg(&rowB[j]);
        float a0, a1, a2, a3, c0, c1, c2, c3;
        asm("mov.b64 {%0, %1}, %2;" : "=f"(a0), "=f"(a1) : "l"(xA2[2 * j]));
        asm("mov.b64 {%0, %1}, %2;" : "=f"(a2), "=f"(a3) : "l"(xA2[2 * j + 1]));
        asm("mov.b64 {%0, %1}, %2;" : "=f"(c0), "=f"(c1) : "l"(xB2[2 * j]));
        asm("mov.b64 {%0, %1}, %2;" : "=f"(c2), "=f"(c3) : "l"(xB2[2 * j + 1]));
        opA[(4 * j + 0) * HW] = __fadd_rn(a0, __fsub_rn(qA.x, a0));
        opA[(4 * j + 1) * HW] = __fadd_rn(a1, __fsub_rn(qA.y, a1));
        opA[(4 * j + 2) * HW] = __fadd_rn(a2, __fsub_rn(qA.z, a2));
        opA[(4 * j + 3) * HW] = __fadd_rn(a3, __fsub_rn(qA.w, a3));
        opB[(4 * j + 0) * HW] = __fadd_rn(c0, __fsub_rn(qB.x, c0));
        opB[(4 * j + 1) * HW] = __fadd_rn(c1, __fsub_rn(qB.y, c1));
        opB[(4 * j + 2) * HW] = __fadd_rn(c2, __fsub_rn(qB.z, c2));
        opB[(4 * j + 3) * HW] = __fadd_rn(c3, __fsub_rn(qB.w, c3));
    }
}

extern "C" void kernel_launch(void* const* d_in, const int* in_sizes, int n_in,
                              void* d_out, int out_size) {
    const float* x  = (const float*)d_in[0];
    const float* cb = (const float*)d_in[1];
    if (n_in >= 2 && in_sizes[0] == NUM_K * DIM && in_sizes[1] == NVEC * DIM) {
        const float* t = x; x = cb; cb = t;
    }
    float* out = (float*)d_out;

    esq_kernel<<<(NUM_K + 127) / 128, 128>>>(cb);
    vq_kernel<<<NVEC / VPB, TPB>>>(x, cb, out);
}